// round 5
// baseline (speedup 1.0000x reference)
#include <cuda_runtime.h>

#define NN 20000
#define FF 256
#define RR 8
#define HH 4
#define UU 64
#define BB 4
#define CC 32   // R*H
#define EE 320000
#define NBLK 79  // ceil(NN/256)

typedef unsigned long long ull;

// ---------------- f32x2 packed math helpers ----------------
__device__ __forceinline__ ull splat2(float v) {
    ull r; asm("mov.b64 %0, {%1, %1};" : "=l"(r) : "f"(v)); return r;
}
__device__ __forceinline__ ull pack2(float lo, float hi) {
    ull r; asm("mov.b64 %0, {%1, %2};" : "=l"(r) : "f"(lo), "f"(hi)); return r;
}
__device__ __forceinline__ void fma2(ull& d, ull a, ull b) {
    asm("fma.rn.f32x2 %0, %1, %2, %0;" : "+l"(d) : "l"(a), "l"(b));
}
__device__ __forceinline__ ull mul2(ull a, ull b) {
    ull d; asm("mul.rn.f32x2 %0, %1, %2;" : "=l"(d) : "l"(a), "l"(b)); return d;
}
__device__ __forceinline__ void unpk2(float& lo, float& hi, ull v) {
    asm("mov.b64 {%0, %1}, %2;" : "=f"(lo), "=f"(hi) : "l"(v));
}

// ---------------- device scratch ----------------
__device__ float  g_y[NN * BB * UU];   // y[n][u*4 + b]  (interleaved, 20.48 MB)
__device__ float  g_qk[NN * 64];       // [n][c] c<32: q(c=r*4+h), c>=32: k
__device__ float  g_wqk[FF * 64];      // [f][c] k-major weight for qk GEMM
__device__ int    g_deg[NN];           // zero at init; re-zeroed by k_scan each call
__device__ int    g_off[NN + 1];
__device__ int    g_cur[NN];
__device__ int    g_bsum[NBLK];        // 0 = not ready; -(sum+1) = ready. reset by k_scatter
__device__ int    g_packed[EE];        // src | (rel<<16), CSR-sorted by dst

// ---------------- static stream/event bootstrap ----------------
static cudaStream_t s_s1 = 0, s_s2 = 0;
static cudaEvent_t  s_evRoot = 0, s_evMisc = 0, s_evA = 0, s_evB = 0;
static bool s_forkOK = false;
namespace {
struct Boot {
    Boot() {
        bool ok = true;
        ok &= (cudaStreamCreateWithFlags(&s_s1, cudaStreamNonBlocking) == cudaSuccess);
        ok &= (cudaStreamCreateWithFlags(&s_s2, cudaStreamNonBlocking) == cudaSuccess);
        ok &= (cudaEventCreateWithFlags(&s_evRoot, cudaEventDisableTiming) == cudaSuccess);
        ok &= (cudaEventCreateWithFlags(&s_evMisc, cudaEventDisableTiming) == cudaSuccess);
        ok &= (cudaEventCreateWithFlags(&s_evA, cudaEventDisableTiming) == cudaSuccess);
        ok &= (cudaEventCreateWithFlags(&s_evB, cudaEventDisableTiming) == cudaSuccess);
        s_forkOK = ok;
    }
} s_boot;
}

// ---------------- K0: prep (blocks 0..31) + hist (blocks 32..344) ----------
#define HBLK ((EE / 4 + 255) / 256)   // 313
__global__ void k_misc(const float* __restrict__ coeff,
                       const float* __restrict__ basis,
                       const float* __restrict__ aq,
                       const float* __restrict__ ak,
                       const int* __restrict__ dst) {
    int bid = blockIdx.x, t = threadIdx.x;
    if (bid < 32) {
        // ---- qk weight build: wqk[f][c] ----
        int idx = bid * 256 + t;      // < 8192 = CC*FF exactly
        int c = idx >> 8;
        int f = idx & 255;
        float sq = 0.f, sk = 0.f;
#pragma unroll
        for (int b = 0; b < BB; ++b) {
            const float* bp = basis + (b * FF + f) * UU;
            const float* aqc = aq + c * UU;
            const float* akc = ak + c * UU;
            float dq = 0.f, dk = 0.f;
#pragma unroll 8
            for (int u = 0; u < UU; ++u) {
                float bv = bp[u];
                dq += bv * aqc[u];
                dk += bv * akc[u];
            }
            float cb = coeff[c * BB + b];
            sq += cb * dq;
            sk += cb * dk;
        }
        g_wqk[f * 64 + c]      = sq;
        g_wqk[f * 64 + 32 + c] = sk;
    } else {
        // ---- degree histogram ----
        int j = (bid - 32) * 256 + t;
        if (j < EE / 4) {
            int4 d4 = ((const int4*)dst)[j];
            atomicAdd(&g_deg[d4.x], 1);
            atomicAdd(&g_deg[d4.y], 1);
            atomicAdd(&g_deg[d4.z], 1);
            atomicAdd(&g_deg[d4.w], 1);
        }
    }
}

// ---------------- K1: generic 128x64 FFMA2 GEMM ----------------
#define GROWS 128
#define KC 128
#define XPAD 132
#define GEMM_SMEM ((KC * XPAD + KC * 64) * 4)

__global__ __launch_bounds__(256, 2) void k_gemm(const float* __restrict__ x,
                                                 const float* __restrict__ w,
                                                 float* __restrict__ out,
                                                 int ostride, int cmul, int cadd0,
                                                 int bstride, int caddstep) {
    extern __shared__ float sm[];
    float* xs = sm;                 // [KC][XPAD] transposed x chunk
    float* ws = sm + KC * XPAD;     // [KC][64]
    int tid = threadIdx.x;
    int tx = tid & 15, ty = tid >> 4;
    int m0 = blockIdx.x * GROWS;
    const float* wb = w + (size_t)blockIdx.y * bstride;
    int cadd = cadd0 + blockIdx.y * caddstep;

    ull acc[4][4];
#pragma unroll
    for (int i = 0; i < 4; ++i)
#pragma unroll
        for (int j = 0; j < 4; ++j) acc[i][j] = 0ull;

    for (int kc = 0; kc < 2; ++kc) {
        if (kc) __syncthreads();
        const float4* w4 = (const float4*)(wb + kc * KC * 64);
        float4* ws4 = (float4*)ws;
        for (int i = tid; i < KC * 16; i += 256) ws4[i] = w4[i];
        const float4* x4 = (const float4*)x;
        for (int i = tid; i < GROWS * 32; i += 256) {
            int row = i >> 5, k4 = i & 31;
            int n = m0 + row;
            float4 v = make_float4(0.f, 0.f, 0.f, 0.f);
            if (n < NN) v = x4[n * 64 + kc * 32 + k4];
            xs[(k4 * 4 + 0) * XPAD + row] = v.x;
            xs[(k4 * 4 + 1) * XPAD + row] = v.y;
            xs[(k4 * 4 + 2) * XPAD + row] = v.z;
            xs[(k4 * 4 + 3) * XPAD + row] = v.w;
        }
        __syncthreads();

        const float* wp = ws + tx * 4;
        const float* xp = xs + ty * 8;
#pragma unroll 8
        for (int k = 0; k < KC; ++k) {
            float4 bv = *(const float4*)(wp + k * 64);
            const float* xr = xp + k * XPAD;
            ull a0 = *(const ull*)(xr);
            ull a1 = *(const ull*)(xr + 2);
            ull a2 = *(const ull*)(xr + 4);
            ull a3 = *(const ull*)(xr + 6);
            ull s0 = splat2(bv.x), s1 = splat2(bv.y),
                s2 = splat2(bv.z), s3 = splat2(bv.w);
            fma2(acc[0][0], a0, s0); fma2(acc[1][0], a1, s0);
            fma2(acc[2][0], a2, s0); fma2(acc[3][0], a3, s0);
            fma2(acc[0][1], a0, s1); fma2(acc[1][1], a1, s1);
            fma2(acc[2][1], a2, s1); fma2(acc[3][1], a3, s1);
            fma2(acc[0][2], a0, s2); fma2(acc[1][2], a1, s2);
            fma2(acc[2][2], a2, s2); fma2(acc[3][2], a3, s2);
            fma2(acc[0][3], a0, s3); fma2(acc[1][3], a1, s3);
            fma2(acc[2][3], a2, s3); fma2(acc[3][3], a3, s3);
        }
    }

    int col0 = tx * 4;
#pragma unroll
    for (int ip = 0; ip < 4; ++ip) {
        float lo[4], hi[4];
#pragma unroll
        for (int j = 0; j < 4; ++j) unpk2(lo[j], hi[j], acc[ip][j]);
        int n0 = m0 + ty * 8 + ip * 2;
        if (n0 < NN) {
            float* o = out + (size_t)n0 * ostride + cadd;
#pragma unroll
            for (int j = 0; j < 4; ++j) o[(col0 + j) * cmul] = lo[j];
        }
        if (n0 + 1 < NN) {
            float* o = out + (size_t)(n0 + 1) * ostride + cadd;
#pragma unroll
            for (int j = 0; j < 4; ++j) o[(col0 + j) * cmul] = hi[j];
        }
    }
}

// ---------------- K2: single-pass scan with sentinel lookback ----------------
// g_bsum[b]: 0 = not ready (reset by k_scatter / static init); -(sum+1) = ready.
// Also self-zeroes g_deg for the next graph replay (deterministic).
__global__ __launch_bounds__(256) void k_scan() {
    int t = threadIdx.x, lane = t & 31, wid = t >> 5, bid = blockIdx.x;
    int i = bid * 256 + t;
    int v = (i < NN) ? g_deg[i] : 0;
    int inc = v;
#pragma unroll
    for (int o = 1; o < 32; o <<= 1) {
        int u = __shfl_up_sync(0xffffffffu, inc, o);
        if (lane >= o) inc += u;
    }
    __shared__ int ws[8], ws2[8], s_base;
    if (lane == 31) ws[wid] = inc;
    __syncthreads();
    // publish block total FIRST (before any spin)
    if (t == 0) {
        int btot = 0;
#pragma unroll
        for (int w = 0; w < 8; ++w) btot += ws[w];
        atomicExch(&g_bsum[bid], -(btot + 1));
    }
    // lookback: thread t spins on predecessor t (t < bid <= 78 < 256)
    int part = 0;
    if (t < bid) {
        volatile int* vb = g_bsum;
        int sv;
        do { sv = vb[t]; } while (sv >= 0);
        part = -sv - 1;
    }
#pragma unroll
    for (int o = 16; o; o >>= 1) part += __shfl_xor_sync(0xffffffffu, part, o);
    if (lane == 0) ws2[wid] = part;
    __syncthreads();
    if (t == 0) {
        int b = 0;
#pragma unroll
        for (int w = 0; w < 8; ++w) b += ws2[w];
        s_base = b;
    }
    __syncthreads();
    int wpre = 0;
#pragma unroll
    for (int w = 0; w < 8; ++w) wpre += (w < wid) ? ws[w] : 0;
    int excl = s_base + wpre + inc - v;
    if (i < NN) { g_off[i] = excl; g_cur[i] = excl; g_deg[i] = 0; }
    if (bid == NBLK - 1 && t == 255) g_off[NN] = EE;
}

// ---------------- K3: scatter (packed), x4 vectorized + g_bsum reset -------
__global__ void k_scatter(const int* __restrict__ src,
                          const int* __restrict__ dst,
                          const int* __restrict__ rel) {
    int j = blockIdx.x * blockDim.x + threadIdx.x;
    if (j < EE / 4) {
        int4 s4 = ((const int4*)src)[j];
        int4 d4 = ((const int4*)dst)[j];
        int4 r4 = ((const int4*)rel)[j];
        int p;
        p = atomicAdd(&g_cur[d4.x], 1); g_packed[p] = s4.x | (r4.x << 16);
        p = atomicAdd(&g_cur[d4.y], 1); g_packed[p] = s4.y | (r4.y << 16);
        p = atomicAdd(&g_cur[d4.z], 1); g_packed[p] = s4.z | (r4.z << 16);
        p = atomicAdd(&g_cur[d4.w], 1); g_packed[p] = s4.w | (r4.w << 16);
    }
    if (blockIdx.x == 0 && threadIdx.x < NBLK) g_bsum[threadIdx.x] = 0;
}

// ---------------- K4: fused online-softmax aggregation, software-pipelined --
__global__ __launch_bounds__(256) void k_agg(const float* __restrict__ coeff,
                                             float* __restrict__ out) {
    __shared__ __align__(16) float cf[CC * BB];  // cf[(r*4+h)*4 + b]
    int tid = threadIdx.x;
    if (tid < CC * BB) cf[tid] = coeff[tid];
    __syncthreads();

    int lane = tid & 31, w = tid >> 5;
    int n = blockIdx.x * 8 + w;
    if (n >= NN) return;

    int beg = g_off[n], end = g_off[n + 1];
    if (beg == end) {
        out[n * UU + lane] = 0.f;
        out[n * UU + 32 + lane] = 0.f;
        return;
    }

    const float* kn = g_qk + n * 64 + 32;

    ull acc[4][2][2];  // [head][u-half][b-pair]
#pragma unroll
    for (int a = 0; a < 4; ++a)
#pragma unroll
        for (int hf = 0; hf < 2; ++hf) { acc[a][hf][0] = 0ull; acc[a][hf][1] = 0ull; }

    float mx[4], dn[4];
#pragma unroll
    for (int a = 0; a < 4; ++a) { mx[a] = __int_as_float(0xff800000); dn[a] = 0.f; }

    // ---- pipeline stage A: fully loaded edge ----
    int pkA = g_packed[beg];
    int sA = pkA & 0xFFFF, rA = pkA >> 16;
    float4 qA  = *(const float4*)(g_qk + sA * 64 + rA * 4);
    float4 kkA = *(const float4*)(kn + rA * 4);
    const float4* yrA = (const float4*)(g_y + (size_t)sA * 256);
    float4 y0A = yrA[lane];
    float4 y1A = yrA[32 + lane];

    for (int e = beg; e < end; ++e) {
        // ---- prefetch stage B (edge e+1): loads in flight during compute ----
        int pkB = pkA, sB = sA, rB = rA;
        float4 qB = qA, kkB = kkA, y0B = y0A, y1B = y1A;
        if (e + 1 < end) {
            pkB = g_packed[e + 1];
            sB = pkB & 0xFFFF; rB = pkB >> 16;
            qB  = *(const float4*)(g_qk + sB * 64 + rB * 4);
            kkB = *(const float4*)(kn + rB * 4);
            const float4* yrB = (const float4*)(g_y + (size_t)sB * 256);
            y0B = yrB[lane];
            y1B = yrB[32 + lane];
        }

        // ---- compute edge A ----
        float l[4];
        l[0] = qA.x + kkA.x; l[0] = l[0] > 0.f ? l[0] : 0.01f * l[0];
        l[1] = qA.y + kkA.y; l[1] = l[1] > 0.f ? l[1] : 0.01f * l[1];
        l[2] = qA.z + kkA.z; l[2] = l[2] > 0.f ? l[2] : 0.01f * l[2];
        l[3] = qA.w + kkA.w; l[3] = l[3] > 0.f ? l[3] : 0.01f * l[3];

        bool resc = false;
        float nmx[4];
#pragma unroll
        for (int a = 0; a < 4; ++a) {
            nmx[a] = fmaxf(mx[a], l[a]);
            resc |= (nmx[a] != mx[a]);
        }
        if (resc) {  // warp-uniform branch
#pragma unroll
            for (int a = 0; a < 4; ++a) {
                float sc = __expf(mx[a] - nmx[a]);  // exp(-inf)=0 on first edge
                dn[a] *= sc;
                ull sc2 = splat2(sc);
                acc[a][0][0] = mul2(acc[a][0][0], sc2);
                acc[a][0][1] = mul2(acc[a][0][1], sc2);
                acc[a][1][0] = mul2(acc[a][1][0], sc2);
                acc[a][1][1] = mul2(acc[a][1][1], sc2);
                mx[a] = nmx[a];
            }
        }

        float wv[4];
#pragma unroll
        for (int a = 0; a < 4; ++a) {
            wv[a] = __expf(l[a] - mx[a]);
            dn[a] += wv[a];
        }

        ull y00 = pack2(y0A.x, y0A.y), y01 = pack2(y0A.z, y0A.w);
        ull y10 = pack2(y1A.x, y1A.y), y11 = pack2(y1A.z, y1A.w);
        const ull* cr = (const ull*)(cf + rA * 16);
#pragma unroll
        for (int a = 0; a < 4; ++a) {
            ull wa = splat2(wv[a]);
            ull c0 = mul2(wa, cr[a * 2]);
            ull c1 = mul2(wa, cr[a * 2 + 1]);
            fma2(acc[a][0][0], c0, y00);
            fma2(acc[a][0][1], c1, y01);
            fma2(acc[a][1][0], c0, y10);
            fma2(acc[a][1][1], c1, y11);
        }

        // ---- rotate B -> A ----
        pkA = pkB; sA = sB; rA = rB;
        qA = qB; kkA = kkB; y0A = y0B; y1A = y1B;
    }

    float o0 = 0.f, o1 = 0.f;
#pragma unroll
    for (int a = 0; a < 4; ++a) {
        float inv = 1.f / fmaxf(dn[a], 1e-16f);
        float l0, h0, l1, h1, l2, h2, l3, h3;
        unpk2(l0, h0, acc[a][0][0]);
        unpk2(l1, h1, acc[a][0][1]);
        unpk2(l2, h2, acc[a][1][0]);
        unpk2(l3, h3, acc[a][1][1]);
        o0 += inv * ((l0 + h0) + (l1 + h1));
        o1 += inv * ((l2 + h2) + (l3 + h3));
    }
    out[n * UU + lane] = 0.25f * o0;
    out[n * UU + 32 + lane] = 0.25f * o1;
}

// ---------------- launch ----------------
extern "C" void kernel_launch(void* const* d_in, const int* in_sizes, int n_in,
                              void* d_out, int out_size) {
    const float* x     = (const float*)d_in[0];
    const float* basis = (const float*)d_in[1];
    const float* coeff = (const float*)d_in[2];
    const float* aq    = (const float*)d_in[3];
    const float* ak    = (const float*)d_in[4];
    const int*   src   = (const int*)d_in[5];
    const int*   dst   = (const int*)d_in[6];
    const int*   rel   = (const int*)d_in[7];
    float* out = (float*)d_out;

    float* d_y;   cudaGetSymbolAddress((void**)&d_y, g_y);
    float* d_qk;  cudaGetSymbolAddress((void**)&d_qk, g_qk);
    float* d_wqk; cudaGetSymbolAddress((void**)&d_wqk, g_wqk);

    cudaFuncSetAttribute(k_gemm, cudaFuncAttributeMaxDynamicSharedMemorySize, GEMM_SMEM);

    cudaStream_t s1 = 0, s2 = 0;
    bool fork = s_forkOK;
    if (fork) {
        s1 = s_s1; s2 = s_s2;
        cudaEventRecord(s_evRoot, 0);
        cudaStreamWaitEvent(s1, s_evRoot, 0);
        cudaStreamWaitEvent(s2, s_evRoot, 0);
    }

    // --- side stream 2: y GEMM (independent of everything else) ---
    k_gemm<<<dim3((NN + GROWS - 1) / GROWS, BB), 256, GEMM_SMEM, s2>>>(
        x, basis, d_y, 256, 4, 0, FF * UU, 1);

    // --- main stream: prep + hist fused ---
    k_misc<<<32 + HBLK, 256>>>(coeff, basis, aq, ak, dst);
    if (fork) {
        cudaEventRecord(s_evMisc, 0);
        cudaStreamWaitEvent(s1, s_evMisc, 0);
    }

    // --- side stream 1: qk GEMM (needs g_wqk from misc) ---
    k_gemm<<<dim3((NN + GROWS - 1) / GROWS, 1), 256, GEMM_SMEM, s1>>>(
        x, d_wqk, d_qk, 64, 1, 0, 0, 0);

    if (fork) {
        cudaEventRecord(s_evA, s1);
        cudaEventRecord(s_evB, s2);
    }

    // --- main stream: scan + scatter ---
    k_scan<<<NBLK, 256>>>();
    k_scatter<<<(EE / 4 + 255) / 256, 256>>>(src, dst, rel);

    if (fork) {
        cudaStreamWaitEvent(0, s_evA, 0);
        cudaStreamWaitEvent(0, s_evB, 0);
    }
    k_agg<<<(NN + 7) / 8, 256>>>(coeff, out);
}